// round 5
// baseline (speedup 1.0000x reference)
#include <cuda_runtime.h>

#define HDIM 512
#define BATCH 256
#define TLEN 512
#define NSTEPS 511          // steps use trg[:, 0..510]
#define FC1_N 1024
#define FC2_N 32000

#define NCTA 128
#define CTA_THREADS 512
#define KCOLS 16            // k-columns per CTA (8 k-pairs)
#define BTILE 64            // batch rows per CTA

// dynamic smem: W slice [512][64] floats + h chunk [32][64] u64 (duplicated)
#define SW_FLOATS (HDIM * 64)
#define SMEM_BYTES (SW_FLOATS * 4 + 32 * 64 * 8)

// -------- persistent device scratch (no allocations allowed) --------
__device__ float g_ht[2][HDIM * BATCH];   // hidden transposed [k][b], dbl-buffered
__device__ float g_hlast[BATCH * HDIM];   // final hidden, [b][k]
__device__ float g_z[BATCH * FC1_N];      // fc1 output
__device__ unsigned int g_arrive;         // grid barrier arrival counter
__device__ unsigned int g_gen;            // grid barrier generation

// -------- packed fp32x2 helpers --------
__device__ __forceinline__ unsigned long long pack2(float lo, float hi) {
    unsigned long long r;
    asm("mov.b64 %0, {%1, %2};" : "=l"(r) : "f"(lo), "f"(hi));
    return r;
}
__device__ __forceinline__ void unpack2(unsigned long long v, float& lo, float& hi) {
    asm("mov.b64 {%0, %1}, %2;" : "=f"(lo), "=f"(hi) : "l"(v));
}
__device__ __forceinline__ void ffma2(unsigned long long& d,
                                      unsigned long long a, unsigned long long b) {
    asm("fma.rn.f32x2 %0, %1, %2, %0;" : "+l"(d) : "l"(a), "l"(b));
}
__device__ __forceinline__ unsigned int ld_acq(const unsigned int* p) {
    unsigned int v;
    asm volatile("ld.global.acquire.gpu.b32 %0, [%1];" : "=r"(v) : "l"(p));
    return v;
}
__device__ __forceinline__ float sigmoidf_(float x) {
    return 1.0f / (1.0f + expf(-x));
}
__device__ __forceinline__ float tanhf_(float x) {
    return 1.0f - 2.0f / (expf(2.0f * x) + 1.0f);
}

// -------- init: zero ht[0], reset barrier --------
__global__ void zero_state() {
    int i = blockIdx.x * blockDim.x + threadIdx.x;
    int stride = gridDim.x * blockDim.x;
    for (int j = i; j < HDIM * BATCH; j += stride) g_ht[0][j] = 0.0f;
    if (i == 0) { g_arrive = 0u; g_gen = 0u; }
}

// ============================================================================
// Persistent LSTM: all 511 timesteps in one kernel.
// Grid 128 CTAs (32 k-tiles x 4 b-tiles), 512 threads, 1 CTA/SM.
// CTA tile: 64 batch x 16 k-cols (x4 gates), FULL K=512 (no split-K).
// W slice (64 gate-cols x 512 K = 131kB) persists in SMEM for all steps,
// layout [kk][cc][g] packed as f32x2 so 4 gate weights = 2x LDS.128.
// Thread: 1 batch x 2 k x 4 gates (4 f32x2 accs); c held in registers.
// Steps separated by an in-kernel grid barrier; h exchanged via g_ht (L2,
// __ldcg/__stcg to bypass non-coherent L1).
// ============================================================================
__global__ __launch_bounds__(CTA_THREADS, 1)
void lstm_persistent(const int* __restrict__ trg,
                     const float* __restrict__ w_hh,   // (2048, 512) row-major
                     const float* __restrict__ w_ih,   // (2048, 1)
                     const float* __restrict__ b_ih,   // (2048,)
                     const float* __restrict__ b_hh)   // (2048,)
{
    extern __shared__ unsigned char dynsmem[];
    float* sW = (float*)dynsmem;                                  // [512][64]
    unsigned long long* sH = (unsigned long long*)(dynsmem + SW_FLOATS * 4); // [32][64]
    const unsigned long long* sWu = (const unsigned long long*)sW;

    const int t   = threadIdx.x;
    const int bid = blockIdx.x;
    const int kx  = bid & 31;          // 32 k-tiles
    const int by  = bid >> 5;          // 4 b-tiles
    const int k0  = kx * KCOLS;
    const int b0  = by * BTILE;

    const int cc = t & 7;              // k-pair 0..7
    const int bl = t >> 3;             // batch lane 0..63
    const int b  = b0 + bl;

    // ---- preload W slice into smem, layout float[kk][cc*8 + g*2 + half] ----
    {
        const int col = t & 63;        // 0..63 -> gate g, col j within tile
        const int g   = col >> 4;
        const int j   = col & 15;
        const int ks  = (t >> 6) * 64; // kk slice 0..448
        const float* src = w_hh + (size_t)(g * HDIM + k0 + j) * HDIM + ks;
        const int fcol = (j >> 1) * 8 + g * 2 + (j & 1);
#pragma unroll
        for (int q = 0; q < 64; q += 4) {
            float4 v = *(const float4*)(src + q);
            sW[(ks + q + 0) * 64 + fcol] = v.x;
            sW[(ks + q + 1) * 64 + fcol] = v.y;
            sW[(ks + q + 2) * 64 + fcol] = v.z;
            sW[(ks + q + 3) * 64 + fcol] = v.w;
        }
    }

    // ---- per-thread constants: bias + w_ih for 4 gates x 2 k ----
    float bias_lo[4], bias_hi[4], wih_lo[4], wih_hi[4];
#pragma unroll
    for (int g = 0; g < 4; g++) {
        int r = g * HDIM + k0 + 2 * cc;
        float2 bi2 = *(const float2*)(b_ih + r);
        float2 bh2 = *(const float2*)(b_hh + r);
        float2 wi2 = *(const float2*)(w_ih + r);
        bias_lo[g] = bi2.x + bh2.x;  bias_hi[g] = bi2.y + bh2.y;
        wih_lo[g]  = wi2.x;          wih_hi[g]  = wi2.y;
    }

    float c_lo = 0.0f, c_hi = 0.0f;    // cell state lives in registers

    // h-chunk staging map: thread loads 4 floats of ht row (kc+skk)
    const int skk = t >> 4;            // 0..31
    const int sbq = t & 15;            // 0..15 -> floats sbq*4..+3

    __syncthreads();                   // W resident

#pragma unroll 1
    for (int s = 0; s < NSTEPS; s++) {
        const float* __restrict__ ht_in  = g_ht[s & 1];
        float*       __restrict__ ht_out = g_ht[(s & 1) ^ 1];

        const float x = (float)__ldg(&trg[b * TLEN + s]);
        unsigned long long acc[4];
#pragma unroll
        for (int g = 0; g < 4; g++)
            acc[g] = pack2(fmaf(x, wih_lo[g], bias_lo[g]),
                           fmaf(x, wih_hi[g], bias_hi[g]));

#pragma unroll 1
        for (int kc = 0; kc < HDIM; kc += 32) {
            // stage h chunk (duplicated f32x2), bypass L1 (cross-SM producer)
            float4 hv = __ldcg((const float4*)(ht_in + (size_t)(kc + skk) * BATCH
                                               + b0 + sbq * 4));
            sH[skk * 64 + sbq * 4 + 0] = pack2(hv.x, hv.x);
            sH[skk * 64 + sbq * 4 + 1] = pack2(hv.y, hv.y);
            sH[skk * 64 + sbq * 4 + 2] = pack2(hv.z, hv.z);
            sH[skk * 64 + sbq * 4 + 3] = pack2(hv.w, hv.w);
            __syncthreads();

#pragma unroll
            for (int kk = 0; kk < 32; kk++) {
                unsigned long long h2 = sH[kk * 64 + bl];
                const unsigned long long* wr = sWu + (size_t)(kc + kk) * 32 + cc * 4;
                ulonglong2 wa = *(const ulonglong2*)(wr);      // gates 0,1
                ulonglong2 wb = *(const ulonglong2*)(wr + 2);  // gates 2,3
                ffma2(acc[0], wa.x, h2);
                ffma2(acc[1], wa.y, h2);
                ffma2(acc[2], wb.x, h2);
                ffma2(acc[3], wb.y, h2);
            }
            __syncthreads();
        }

        // ---- pointwise LSTM update (gate order i, f, g, o) ----
        float iv0, iv1, fv0, fv1, gv0, gv1, ov0, ov1;
        unpack2(acc[0], iv0, iv1);
        unpack2(acc[1], fv0, fv1);
        unpack2(acc[2], gv0, gv1);
        unpack2(acc[3], ov0, ov1);

        float i0 = sigmoidf_(iv0), f0 = sigmoidf_(fv0), gg0 = tanhf_(gv0), o0 = sigmoidf_(ov0);
        float i1 = sigmoidf_(iv1), f1 = sigmoidf_(fv1), gg1 = tanhf_(gv1), o1 = sigmoidf_(ov1);
        c_lo = fmaf(f0, c_lo, i0 * gg0);
        c_hi = fmaf(f1, c_hi, i1 * gg1);
        float h0 = o0 * tanhf_(c_lo);
        float h1 = o1 * tanhf_(c_hi);

        const int kcol = k0 + 2 * cc;
        __stcg(&ht_out[(size_t)kcol * BATCH + b], h0);
        __stcg(&ht_out[(size_t)(kcol + 1) * BATCH + b], h1);
        if (s == NSTEPS - 1) {
            g_hlast[(size_t)b * HDIM + kcol]     = h0;
            g_hlast[(size_t)b * HDIM + kcol + 1] = h1;
        }

        // ---- grid barrier between steps ----
        if (s < NSTEPS - 1) {
            __syncthreads();
            if (t == 0) {
                __threadfence();
                unsigned prev = atomicAdd(&g_arrive, 1u);
                if (prev == (unsigned)(NCTA - 1)) {
                    atomicExch(&g_arrive, 0u);
                    __threadfence();
                    atomicExch(&g_gen, (unsigned)(s + 1));
                } else {
                    while (ld_acq(&g_gen) < (unsigned)(s + 1)) { }
                }
            }
            __syncthreads();
        }
    }
}

// ============================================================================
// Fused GEMM head: C[M,N] = A[M,K] @ W[N,K]^T + bias, optional ReLU.
// 32(M) x 128(N) tile, 256 threads, FFMA2. asel: 0 -> A = g_hlast, 1 -> A = g_z.
// ============================================================================
__global__ __launch_bounds__(256)
void fc_gemm(int asel,
             const float* __restrict__ W,
             const float* __restrict__ bias,
             float* __restrict__ C,
             int K, int N, int do_relu)
{
    __shared__ float  sW[32 * 128];
    __shared__ float2 sH2[32 * 33];

    const float* __restrict__ A = (asel == 0) ? &g_hlast[0] : &g_z[0];

    const int t  = threadIdx.x;
    const int n0 = blockIdx.x * 128;
    const int m0 = blockIdx.y * 32;

    const int cc  = t & 15;
    const int bg  = t >> 4;
    const int bi0 = bg * 2;

    unsigned long long acc[2][4];
#pragma unroll
    for (int g = 0; g < 4; g++) {
        float2 b2 = *(const float2*)(bias + n0 + g * 32 + 2 * cc);
        acc[0][g] = pack2(b2.x, b2.y);
        acc[1][g] = pack2(b2.x, b2.y);
    }

    const int r128 = t >> 1;
    const int hf   = t & 1;
    const float4* __restrict__ Wrow = (const float4*)(W + (size_t)(n0 + r128) * K);

    const int hbi = t >> 3;
    const int hk0 = (t & 7) * 4;

    const unsigned long long* sWu = (const unsigned long long*)sW;
    const unsigned long long* sHu = (const unsigned long long*)sH2;

    for (int kc = 0; kc < K; kc += 32) {
        if (kc) __syncthreads();
#pragma unroll
        for (int q = 0; q < 4; q++) {
            float4 v = Wrow[(kc + hf * 16) / 4 + q];
            int kl = hf * 16 + q * 4;
            sW[(kl + 0) * 128 + r128] = v.x;
            sW[(kl + 1) * 128 + r128] = v.y;
            sW[(kl + 2) * 128 + r128] = v.z;
            sW[(kl + 3) * 128 + r128] = v.w;
        }
        float4 hv = *(const float4*)(A + (size_t)(m0 + hbi) * K + kc + hk0);
        sH2[(hk0 + 0) * 33 + hbi] = make_float2(hv.x, hv.x);
        sH2[(hk0 + 1) * 33 + hbi] = make_float2(hv.y, hv.y);
        sH2[(hk0 + 2) * 33 + hbi] = make_float2(hv.z, hv.z);
        sH2[(hk0 + 3) * 33 + hbi] = make_float2(hv.w, hv.w);
        __syncthreads();

#pragma unroll 8
        for (int kk = 0; kk < 32; kk++) {
            unsigned long long h0 = sHu[kk * 33 + bi0];
            unsigned long long h1 = sHu[kk * 33 + bi0 + 1];
#pragma unroll
            for (int g = 0; g < 4; g++) {
                unsigned long long w = sWu[kk * 64 + g * 16 + cc];
                ffma2(acc[0][g], w, h0);
                ffma2(acc[1][g], w, h1);
            }
        }
    }

#pragma unroll
    for (int bb = 0; bb < 2; bb++) {
        int m = m0 + bi0 + bb;
#pragma unroll
        for (int g = 0; g < 4; g++) {
            float lo, hi;
            unpack2(acc[bb][g], lo, hi);
            if (do_relu) { lo = fmaxf(lo, 0.0f); hi = fmaxf(hi, 0.0f); }
            *(float2*)(C + (size_t)m * N + n0 + g * 32 + 2 * cc) = make_float2(lo, hi);
        }
    }
}

// ============================================================================
extern "C" void kernel_launch(void* const* d_in, const int* in_sizes, int n_in,
                              void* d_out, int out_size) {
    // metadata order: x, hidden, trg, w_ih, w_hh, b_ih, b_hh, fc1_w, fc1_b, fc2_w, fc2_b
    const int*   trg   = (const int*)  d_in[2];
    const float* w_ih  = (const float*)d_in[3];
    const float* w_hh  = (const float*)d_in[4];
    const float* b_ih  = (const float*)d_in[5];
    const float* b_hh  = (const float*)d_in[6];
    const float* fc1_w = (const float*)d_in[7];
    const float* fc1_b = (const float*)d_in[8];
    const float* fc2_w = (const float*)d_in[9];
    const float* fc2_b = (const float*)d_in[10];
    float* out = (float*)d_out;

    static bool attr_set = false;
    if (!attr_set) {
        cudaFuncSetAttribute(lstm_persistent,
                             cudaFuncAttributeMaxDynamicSharedMemorySize, SMEM_BYTES);
        attr_set = true;
    }

    zero_state<<<128, 256>>>();

    lstm_persistent<<<NCTA, CTA_THREADS, SMEM_BYTES>>>(trg, w_hh, w_ih, b_ih, b_hh);

    // z = relu(h_last @ fc1_w^T + fc1_b)
    void* zptr_sym = nullptr;
    cudaGetSymbolAddress(&zptr_sym, g_z);
    float* zptr = (float*)zptr_sym;
    fc_gemm<<<dim3(FC1_N / 128, BATCH / 32), 256>>>(
        0, fc1_w, fc1_b, zptr, HDIM, FC1_N, 1);

    // out = z @ fc2_w^T + fc2_b
    fc_gemm<<<dim3(FC2_N / 128, BATCH / 32), 256>>>(
        1, fc2_w, fc2_b, out, FC1_N, FC2_N, 0);
}

// round 6
// speedup vs baseline: 2.0569x; 2.0569x over previous
#include <cuda_runtime.h>

#define HDIM 512
#define BATCH 256
#define TLEN 512
#define NSTEPS 511
#define FC1_N 1024
#define FC2_N 32000

typedef unsigned long long u64;

// -------- persistent device scratch --------
__device__ u64   g_wt[32 * 512 * 32];     // 4MB W transformed [kx][k][slot]
__device__ float g_hbuf[2][HDIM * BATCH]; // h transposed [k][b], dbl-buffered
__device__ u64   g_c2[256 * 256];         // c pairs [kpair][b]
__device__ float g_hlast[BATCH * HDIM];   // final h, [b][k]
__device__ float g_z[BATCH * FC1_N];
__device__ u64   g_bias2[1024];           // (b_ih+b_hh) pairs
__device__ u64   g_wih2[1024];            // w_ih pairs

__device__ __forceinline__ u64 pack2(float lo, float hi) {
    u64 r; asm("mov.b64 %0, {%1, %2};" : "=l"(r) : "f"(lo), "f"(hi)); return r;
}
__device__ __forceinline__ void unpack2(u64 v, float& lo, float& hi) {
    asm("mov.b64 {%0, %1}, %2;" : "=f"(lo), "=f"(hi) : "l"(v));
}
__device__ __forceinline__ void ffma2(u64& d, u64 a, u64 b) {
    asm("fma.rn.f32x2 %0, %1, %2, %0;" : "+l"(d) : "l"(a), "l"(b));
}
__device__ __forceinline__ float sigmoidf_(float x) { return 1.0f / (1.0f + expf(-x)); }
__device__ __forceinline__ float tanhf_(float x) { return 1.0f - 2.0f / (expf(2.0f * x) + 1.0f); }

// ---- one-time W transform: slot = cc*4+g holds (W[row][k], W[row+1][k]) ----
__global__ void prep_w(const float* __restrict__ w_hh) {
    int tid = blockIdx.x * blockDim.x + threadIdx.x;   // 0..524287
    int slot = tid & 31, k = (tid >> 5) & 511, kx = tid >> 14;
    int cc = slot >> 2, g = slot & 3;
    int row = g * HDIM + kx * 16 + 2 * cc;
    g_wt[tid] = pack2(w_hh[(size_t)row * HDIM + k], w_hh[(size_t)(row + 1) * HDIM + k]);
}

__global__ void prep_misc(const float* __restrict__ b_ih,
                          const float* __restrict__ b_hh,
                          const float* __restrict__ w_ih) {
    int i = blockIdx.x * blockDim.x + threadIdx.x;
    int n = gridDim.x * blockDim.x;
    for (int j = i; j < HDIM * BATCH; j += n) g_hbuf[0][j] = 0.0f;
    for (int j = i; j < 256 * 256; j += n) g_c2[j] = 0ull;
    for (int j = i; j < 1024; j += n) {
        int r = j * 2;
        g_bias2[j] = pack2(b_ih[r] + b_hh[r], b_ih[r + 1] + b_hh[r + 1]);
        g_wih2[j]  = pack2(w_ih[r], w_ih[r + 1]);
    }
}

// ============================================================================
// One LSTM step. Grid (32 kx, 4 by) = 128 CTAs x 128 threads (1 warp/SMSP).
// CTA: 64 batch x 16 kcols x 4 gates, full K=512. Thread: 4b x 1 kpair x 4g.
// Inner per kk: 2 LDG.128 (W pairs) + 1 LDG.128 (h, 4 batches) + 4 pack (ALU)
// + 16 independent FFMA2. No smem, no syncthreads.
// ============================================================================
__global__ __launch_bounds__(128, 1)
void lstm_step(const int* __restrict__ trg, int s)
{
    const float* __restrict__ h_in  = g_hbuf[s & 1];
    float*       __restrict__ h_out = g_hbuf[(s & 1) ^ 1];

    const int t  = threadIdx.x;
    const int kx = blockIdx.x;          // 0..31
    const int b0 = blockIdx.y * 64;     // 0..3 -> batch base
    const int cc = t & 7;               // k-pair within tile
    const int bg = t >> 3;              // 0..15
    const int bA = b0 + 4 * bg;
    const int kp = kx * 8 + cc;         // global k-pair 0..255
    const int kcol = 2 * kp;

    // acc init: bias + x * w_ih
    u64 acc[4][4];
    {
        float xv[4];
#pragma unroll
        for (int bb = 0; bb < 4; bb++) xv[bb] = (float)trg[(bA + bb) * TLEN + s];
#pragma unroll
        for (int g = 0; g < 4; g++) {
            float bl, bh, wl, wh;
            unpack2(g_bias2[g * 256 + kp], bl, bh);
            unpack2(g_wih2[g * 256 + kp], wl, wh);
#pragma unroll
            for (int bb = 0; bb < 4; bb++)
                acc[bb][g] = pack2(fmaf(xv[bb], wl, bl), fmaf(xv[bb], wh, bh));
        }
    }

    const ulonglong2* __restrict__ wp = (const ulonglong2*)(g_wt + (size_t)kx * 512 * 32);

#pragma unroll 8
    for (int kk = 0; kk < HDIM; kk++) {
        ulonglong2 w01 = wp[kk * 16 + cc * 2];       // gates 0,1
        ulonglong2 w23 = wp[kk * 16 + cc * 2 + 1];   // gates 2,3
        float4 hv = *(const float4*)(h_in + kk * BATCH + bA);
        u64 hd[4];
        hd[0] = pack2(hv.x, hv.x); hd[1] = pack2(hv.y, hv.y);
        hd[2] = pack2(hv.z, hv.z); hd[3] = pack2(hv.w, hv.w);
#pragma unroll
        for (int bb = 0; bb < 4; bb++) {
            ffma2(acc[bb][0], w01.x, hd[bb]);
            ffma2(acc[bb][1], w01.y, hd[bb]);
            ffma2(acc[bb][2], w23.x, hd[bb]);
            ffma2(acc[bb][3], w23.y, hd[bb]);
        }
    }

    // ---- pointwise (gate order i,f,g,o); c pairs in g_c2 ----
    ulonglong2 cold0 = *(const ulonglong2*)(g_c2 + (size_t)kp * 256 + bA);
    ulonglong2 cold1 = *(const ulonglong2*)(g_c2 + (size_t)kp * 256 + bA + 2);
    u64 cold[4] = {cold0.x, cold0.y, cold1.x, cold1.y};
    float hlo[4], hhi[4];
    u64 cnew[4];
#pragma unroll
    for (int bb = 0; bb < 4; bb++) {
        float iv0, iv1, fv0, fv1, gv0, gv1, ov0, ov1, c0, c1;
        unpack2(acc[bb][0], iv0, iv1);
        unpack2(acc[bb][1], fv0, fv1);
        unpack2(acc[bb][2], gv0, gv1);
        unpack2(acc[bb][3], ov0, ov1);
        unpack2(cold[bb], c0, c1);
        float i0 = sigmoidf_(iv0), f0 = sigmoidf_(fv0), gg0 = tanhf_(gv0), o0 = sigmoidf_(ov0);
        float i1 = sigmoidf_(iv1), f1 = sigmoidf_(fv1), gg1 = tanhf_(gv1), o1 = sigmoidf_(ov1);
        c0 = fmaf(f0, c0, i0 * gg0);
        c1 = fmaf(f1, c1, i1 * gg1);
        cnew[bb] = pack2(c0, c1);
        hlo[bb] = o0 * tanhf_(c0);
        hhi[bb] = o1 * tanhf_(c1);
    }
    *(ulonglong2*)(g_c2 + (size_t)kp * 256 + bA)     = make_ulonglong2(cnew[0], cnew[1]);
    *(ulonglong2*)(g_c2 + (size_t)kp * 256 + bA + 2) = make_ulonglong2(cnew[2], cnew[3]);
    *(float4*)(h_out + (size_t)kcol * BATCH + bA)       = make_float4(hlo[0], hlo[1], hlo[2], hlo[3]);
    *(float4*)(h_out + (size_t)(kcol + 1) * BATCH + bA) = make_float4(hhi[0], hhi[1], hhi[2], hhi[3]);
    if (s == NSTEPS - 1) {
#pragma unroll
        for (int bb = 0; bb < 4; bb++)
            *(float2*)(g_hlast + (size_t)(bA + bb) * HDIM + kcol) = make_float2(hlo[bb], hhi[bb]);
    }
}

// ============================================================================
// Fused GEMM head (round-3 proven): C[M,N] = A @ W^T + bias, optional ReLU.
// ============================================================================
__global__ __launch_bounds__(256)
void fc_gemm(int asel, const float* __restrict__ W, const float* __restrict__ bias,
             float* __restrict__ C, int K, int N, int do_relu)
{
    __shared__ float  sW[32 * 128];
    __shared__ float2 sH2[32 * 33];
    const float* __restrict__ A = (asel == 0) ? &g_hlast[0] : &g_z[0];

    const int t = threadIdx.x, n0 = blockIdx.x * 128, m0 = blockIdx.y * 32;
    const int cc = t & 15, bi0 = (t >> 4) * 2;

    u64 acc[2][4];
#pragma unroll
    for (int g = 0; g < 4; g++) {
        float2 b2 = *(const float2*)(bias + n0 + g * 32 + 2 * cc);
        acc[0][g] = pack2(b2.x, b2.y);
        acc[1][g] = pack2(b2.x, b2.y);
    }
    const int r128 = t >> 1, hf = t & 1;
    const float4* __restrict__ Wrow = (const float4*)(W + (size_t)(n0 + r128) * K);
    const int hbi = t >> 3, hk0 = (t & 7) * 4;
    const u64* sWu = (const u64*)sW;
    const u64* sHu = (const u64*)sH2;

    for (int kc = 0; kc < K; kc += 32) {
        if (kc) __syncthreads();
#pragma unroll
        for (int q = 0; q < 4; q++) {
            float4 v = Wrow[(kc + hf * 16) / 4 + q];
            int kl = hf * 16 + q * 4;
            sW[(kl + 0) * 128 + r128] = v.x;
            sW[(kl + 1) * 128 + r128] = v.y;
            sW[(kl + 2) * 128 + r128] = v.z;
            sW[(kl + 3) * 128 + r128] = v.w;
        }
        float4 hv = *(const float4*)(A + (size_t)(m0 + hbi) * K + kc + hk0);
        sH2[(hk0 + 0) * 33 + hbi] = make_float2(hv.x, hv.x);
        sH2[(hk0 + 1) * 33 + hbi] = make_float2(hv.y, hv.y);
        sH2[(hk0 + 2) * 33 + hbi] = make_float2(hv.z, hv.z);
        sH2[(hk0 + 3) * 33 + hbi] = make_float2(hv.w, hv.w);
        __syncthreads();
#pragma unroll 8
        for (int kk = 0; kk < 32; kk++) {
            u64 h0 = sHu[kk * 33 + bi0];
            u64 h1 = sHu[kk * 33 + bi0 + 1];
#pragma unroll
            for (int g = 0; g < 4; g++) {
                u64 w = sWu[kk * 64 + g * 16 + cc];
                ffma2(acc[0][g], w, h0);
                ffma2(acc[1][g], w, h1);
            }
        }
    }
#pragma unroll
    for (int bb = 0; bb < 2; bb++) {
        int m = m0 + bi0 + bb;
#pragma unroll
        for (int g = 0; g < 4; g++) {
            float lo, hi;
            unpack2(acc[bb][g], lo, hi);
            if (do_relu) { lo = fmaxf(lo, 0.0f); hi = fmaxf(hi, 0.0f); }
            *(float2*)(C + (size_t)m * N + n0 + g * 32 + 2 * cc) = make_float2(lo, hi);
        }
    }
}

// ============================================================================
extern "C" void kernel_launch(void* const* d_in, const int* in_sizes, int n_in,
                              void* d_out, int out_size) {
    const int*   trg   = (const int*)  d_in[2];
    const float* w_ih  = (const float*)d_in[3];
    const float* w_hh  = (const float*)d_in[4];
    const float* b_ih  = (const float*)d_in[5];
    const float* b_hh  = (const float*)d_in[6];
    const float* fc1_w = (const float*)d_in[7];
    const float* fc1_b = (const float*)d_in[8];
    const float* fc2_w = (const float*)d_in[9];
    const float* fc2_b = (const float*)d_in[10];
    float* out = (float*)d_out;

    prep_w<<<2048, 256>>>(w_hh);
    prep_misc<<<256, 256>>>(b_ih, b_hh, w_ih);

    dim3 sgrid(32, 4);   // 128 CTAs x 128 threads
    for (int s = 0; s < NSTEPS; s++)
        lstm_step<<<sgrid, 128>>>(trg, s);

    void* zsym = nullptr;
    cudaGetSymbolAddress(&zsym, g_z);
    float* zptr = (float*)zsym;
    fc_gemm<<<dim3(FC1_N / 128, BATCH / 32), 256>>>(0, fc1_w, fc1_b, zptr, HDIM, FC1_N, 1);
    fc_gemm<<<dim3(FC2_N / 128, BATCH / 32), 256>>>(1, fc2_w, fc2_b, out, FC1_N, FC2_N, 0);
}

// round 7
// speedup vs baseline: 2.2563x; 1.0969x over previous
#include <cuda_runtime.h>
#define HDIM 512
#define BATCH 256
#define TLEN 512
#define NSTEPS 511
#define FC1_N 1024
#define FC2_N 32000
typedef unsigned long long u64;

// -------- persistent device scratch --------
__device__ u64   g_wt[32 * 16384];     // 4MB: per-tile W images [kx][kk][half][kp][gl]
__device__ u64   g_htd[2][512 * 256];  // h duplicated (h,h) as u64, [k][b]
__device__ float g_hlast[BATCH * HDIM];
__device__ float g_z[BATCH * FC1_N];
__device__ u64   g_bias2[1024], g_wih2[1024];
__device__ unsigned int g_arrive, g_gen;

__device__ __forceinline__ u64 pack2(float lo, float hi) {
    u64 r; asm("mov.b64 %0, {%1, %2};" : "=l"(r) : "f"(lo), "f"(hi)); return r;
}
__device__ __forceinline__ void unpack2(u64 v, float& lo, float& hi) {
    asm("mov.b64 {%0, %1}, %2;" : "=f"(lo), "=f"(hi) : "l"(v));
}
__device__ __forceinline__ void ffma2(u64& d, u64 a, u64 b) {
    asm("fma.rn.f32x2 %0, %1, %2, %0;" : "+l"(d) : "l"(a), "l"(b));
}
__device__ __forceinline__ ulonglong2 ldcg2(const u64* p) {
    ulonglong2 v;
    asm volatile("ld.global.cg.v2.u64 {%0,%1}, [%2];" : "=l"(v.x), "=l"(v.y) : "l"(p));
    return v;
}
__device__ __forceinline__ void stcg2(u64* p, u64 a, u64 b) {
    asm volatile("st.global.cg.v2.u64 [%0], {%1,%2};" :: "l"(p), "l"(a), "l"(b) : "memory");
}
__device__ __forceinline__ unsigned int ld_acq(const unsigned int* p) {
    unsigned int v;
    asm volatile("ld.global.acquire.gpu.b32 %0, [%1];" : "=r"(v) : "l"(p));
    return v;
}
__device__ __forceinline__ float sigmoidf_(float x) { return 1.0f / (1.0f + expf(-x)); }
__device__ __forceinline__ float tanhf_(float x) { return 1.0f - 2.0f / (expf(2.0f * x) + 1.0f); }

// ---- W transform: g_wt[kx*16384 + kk*32 + half*16 + kp*2 + gl] ----
__global__ void prep_w(const float* __restrict__ w) {
    int tid = blockIdx.x * blockDim.x + threadIdx.x;   // 0..524287
    int i = tid & 16383, kx = tid >> 14;
    int kk = i >> 5, r = i & 31;
    int half = r >> 4, kp = (r >> 1) & 7, gl = r & 1, g = half * 2 + gl;
    int row = g * HDIM + kx * 16 + kp * 2;
    g_wt[tid] = pack2(w[(size_t)row * HDIM + kk], w[(size_t)(row + 1) * HDIM + kk]);
}

__global__ void prep_misc(const float* __restrict__ b_ih,
                          const float* __restrict__ b_hh,
                          const float* __restrict__ w_ih) {
    int i = blockIdx.x * blockDim.x + threadIdx.x;
    int n = gridDim.x * blockDim.x;
    for (int j = i; j < 512 * 256; j += n) g_htd[0][j] = 0ull;
    for (int j = i; j < 1024; j += n) {
        int r = j * 2;
        g_bias2[j] = pack2(b_ih[r] + b_hh[r], b_ih[r + 1] + b_hh[r + 1]);
        g_wih2[j]  = pack2(w_ih[r], w_ih[r + 1]);
    }
    if (i == 0) { g_arrive = 0u; g_gen = 0u; }
}

// ============================================================================
// Persistent LSTM: 128 CTAs (32 kx x 4 by) x 256 thr, 1 CTA/SM.
// W slice resident in smem (131kB). Tile 64b x 16kcols x 4g, K=512.
// Thread: 2b x 1kpair x 4g -> per kk: 3 LDS.128 + 8 FFMA2. c in registers.
// h via global dup-u64 [k][b] (.cg), chunk(32kk)-double-buffered in smem.
// ============================================================================
#define SMEMB (16384 * 8 + 2 * 2048 * 8)   // 163840 B
__global__ __launch_bounds__(256, 1)
void lstm_persist(const int* __restrict__ trg)
{
    extern __shared__ u64 sm[];
    u64* sW = sm;                 // [512kk][32]
    u64* sH = sm + 16384;         // [2][32kk][64b]

    const int t  = threadIdx.x;
    const int kx = blockIdx.x & 31, by = blockIdx.x >> 5;
    const int kp = t & 7, bp = t >> 3;       // kp 0..7, bp 0..31
    const int b0 = by * 64, bA = b0 + 2 * bp;
    const int kcol = kx * 16 + kp * 2;

    // load W slice once
    {
        const u64* ws = g_wt + (size_t)kx * 16384;
        for (int i = 2 * t; i < 16384; i += 512)
            *(ulonglong2*)(sW + i) = *(const ulonglong2*)(ws + i);
    }
    u64 bias[4], wih[4];
#pragma unroll
    for (int g = 0; g < 4; g++) {
        bias[g] = g_bias2[g * 256 + kx * 8 + kp];
        wih[g]  = g_wih2[g * 256 + kx * 8 + kp];
    }
    float cA0 = 0, cA1 = 0, cB0 = 0, cB1 = 0;    // c for 2b x 2k
    const int lr = t >> 3, lc = (t & 7) * 8;      // h loader: row lr, 8 u64 at lc
    __syncthreads();

#pragma unroll 1
    for (int s = 0; s < NSTEPS; s++) {
        const u64* __restrict__ hin  = g_htd[s & 1];
        u64*       __restrict__ hout = g_htd[(s & 1) ^ 1];

        u64 acc[2][4];
        {
            float xA = (float)__ldg(trg + bA * TLEN + s);
            float xB = (float)__ldg(trg + (bA + 1) * TLEN + s);
#pragma unroll
            for (int g = 0; g < 4; g++) {
                float bl, bh, wl, wh;
                unpack2(bias[g], bl, bh); unpack2(wih[g], wl, wh);
                acc[0][g] = pack2(fmaf(xA, wl, bl), fmaf(xA, wh, bh));
                acc[1][g] = pack2(fmaf(xB, wl, bl), fmaf(xB, wh, bh));
            }
        }

        // prologue: chunk 0 -> buf 0
        ulonglong2 pf[4];
        {
            const u64* src = hin + (size_t)lr * 256 + b0 + lc;
#pragma unroll
            for (int q = 0; q < 4; q++) pf[q] = ldcg2(src + 2 * q);
            u64* d = sH + lr * 64 + lc;
#pragma unroll
            for (int q = 0; q < 4; q++) *(ulonglong2*)(d + 2 * q) = pf[q];
        }
        __syncthreads();

#pragma unroll 1
        for (int kc = 0; kc < 16; kc++) {
            if (kc < 15) {
                const u64* src = hin + (size_t)((kc + 1) * 32 + lr) * 256 + b0 + lc;
#pragma unroll
                for (int q = 0; q < 4; q++) pf[q] = ldcg2(src + 2 * q);
            }
            const u64* Hb = sH + (kc & 1) * 2048;
            const u64* Wk = sW + (size_t)kc * 1024;   // (kc*32+kk)*32

            ulonglong2 w0c = *(const ulonglong2*)(Wk + kp * 2);
            ulonglong2 w1c = *(const ulonglong2*)(Wk + 16 + kp * 2);
            ulonglong2 hc  = *(const ulonglong2*)(Hb + bp * 2);
#pragma unroll
            for (int kk = 0; kk < 32; kk++) {
                ulonglong2 w0n, w1n, hn;
                if (kk < 31) {
                    const u64* Wn = Wk + (kk + 1) * 32;
                    w0n = *(const ulonglong2*)(Wn + kp * 2);
                    w1n = *(const ulonglong2*)(Wn + 16 + kp * 2);
                    hn  = *(const ulonglong2*)(Hb + (kk + 1) * 64 + bp * 2);
                }
                ffma2(acc[0][0], w0c.x, hc.x); ffma2(acc[0][1], w0c.y, hc.x);
                ffma2(acc[0][2], w1c.x, hc.x); ffma2(acc[0][3], w1c.y, hc.x);
                ffma2(acc[1][0], w0c.x, hc.y); ffma2(acc[1][1], w0c.y, hc.y);
                ffma2(acc[1][2], w1c.x, hc.y); ffma2(acc[1][3], w1c.y, hc.y);
                if (kk < 31) { w0c = w0n; w1c = w1n; hc = hn; }
            }
            if (kc < 15) {
                u64* d = sH + ((kc + 1) & 1) * 2048 + lr * 64 + lc;
#pragma unroll
                for (int q = 0; q < 4; q++) *(ulonglong2*)(d + 2 * q) = pf[q];
            }
            __syncthreads();
        }

        // ---- pointwise (i,f,g,o) ----
        float hA0, hA1, hB0, hB1;
        {
            float i0, i1, f0, f1, g0, g1, o0, o1;
            unpack2(acc[0][0], i0, i1); unpack2(acc[0][1], f0, f1);
            unpack2(acc[0][2], g0, g1); unpack2(acc[0][3], o0, o1);
            i0 = sigmoidf_(i0); f0 = sigmoidf_(f0); g0 = tanhf_(g0); o0 = sigmoidf_(o0);
            i1 = sigmoidf_(i1); f1 = sigmoidf_(f1); g1 = tanhf_(g1); o1 = sigmoidf_(o1);
            cA0 = fmaf(f0, cA0, i0 * g0); cA1 = fmaf(f1, cA1, i1 * g1);
            hA0 = o0 * tanhf_(cA0); hA1 = o1 * tanhf_(cA1);
        }
        {
            float i0, i1, f0, f1, g0, g1, o0, o1;
            unpack2(acc[1][0], i0, i1); unpack2(acc[1][1], f0, f1);
            unpack2(acc[1][2], g0, g1); unpack2(acc[1][3], o0, o1);
            i0 = sigmoidf_(i0); f0 = sigmoidf_(f0); g0 = tanhf_(g0); o0 = sigmoidf_(o0);
            i1 = sigmoidf_(i1); f1 = sigmoidf_(f1); g1 = tanhf_(g1); o1 = sigmoidf_(o1);
            cB0 = fmaf(f0, cB0, i0 * g0); cB1 = fmaf(f1, cB1, i1 * g1);
            hB0 = o0 * tanhf_(cB0); hB1 = o1 * tanhf_(cB1);
        }
        stcg2(hout + (size_t)kcol * 256 + bA,       pack2(hA0, hA0), pack2(hB0, hB0));
        stcg2(hout + (size_t)(kcol + 1) * 256 + bA, pack2(hA1, hA1), pack2(hB1, hB1));
        if (s == NSTEPS - 1) {
            *(float2*)(g_hlast + (size_t)bA * HDIM + kcol)       = make_float2(hA0, hA1);
            *(float2*)(g_hlast + (size_t)(bA + 1) * HDIM + kcol) = make_float2(hB0, hB1);
        }

        if (s < NSTEPS - 1) {
            __syncthreads();
            if (t == 0) {
                __threadfence();
                unsigned prev = atomicAdd(&g_arrive, 1u);
                if (prev == 127u) {
                    atomicExch(&g_arrive, 0u);
                    __threadfence();
                    atomicExch(&g_gen, (unsigned)(s + 1));
                } else {
                    while (ld_acq(&g_gen) < (unsigned)(s + 1)) { }
                }
            }
            __syncthreads();
        }
    }
}

// ============================================================================
// Fused GEMM head (R3-proven): C = A @ W^T + bias, optional ReLU.
// ============================================================================
__global__ __launch_bounds__(256)
void fc_gemm(int asel, const float* __restrict__ W, const float* __restrict__ bias,
             float* __restrict__ C, int K, int N, int do_relu)
{
    __shared__ float  sW[32 * 128];
    __shared__ float2 sH2[32 * 33];
    const float* __restrict__ A = (asel == 0) ? &g_hlast[0] : &g_z[0];
    const int t = threadIdx.x, n0 = blockIdx.x * 128, m0 = blockIdx.y * 32;
    const int cc = t & 15, bi0 = (t >> 4) * 2;

    u64 acc[2][4];
#pragma unroll
    for (int g = 0; g < 4; g++) {
        float2 b2 = *(const float2*)(bias + n0 + g * 32 + 2 * cc);
        acc[0][g] = pack2(b2.x, b2.y);
        acc[1][g] = pack2(b2.x, b2.y);
    }
    const int r128 = t >> 1, hf = t & 1;
    const float4* __restrict__ Wrow = (const float4*)(W + (size_t)(n0 + r128) * K);
    const int hbi = t >> 3, hk0 = (t & 7) * 4;
    const u64* sWu = (const u64*)sW;
    const u64* sHu = (const u64*)sH2;

    for (int kc = 0; kc < K; kc += 32) {
        if (kc) __syncthreads();
#pragma unroll
        for (int q = 0; q < 4; q++) {
            float4 v = Wrow[(kc + hf * 16) / 4 + q];
            int kl = hf * 16 + q * 4;
            sW[(kl + 0) * 128 + r128] = v.x;
            sW[(kl + 1) * 128 + r128] = v.y;
            sW[(kl + 2) * 128 + r128] = v.z;
            sW[(kl + 3) * 128 + r128] = v.w;
        }
        float4 hv = *(const float4*)(A + (size_t)(m0 + hbi) * K + kc + hk0);
        sH2[(hk0 + 0) * 33 + hbi] = make_float2(hv.x, hv.x);
        sH2[(hk0 + 1) * 33 + hbi] = make_float2(hv.y, hv.y);
        sH2[(hk0 + 2) * 33 + hbi] = make_float2(hv.z, hv.z);
        sH2[(hk0 + 3) * 33 + hbi] = make_float2(hv.w, hv.w);
        __syncthreads();
#pragma unroll 8
        for (int kk = 0; kk < 32; kk++) {
            u64 h0 = sHu[kk * 33 + bi0];
            u64 h1 = sHu[kk * 33 + bi0 + 1];
#pragma unroll
            for (int g = 0; g < 4; g++) {
                u64 w = sWu[kk * 64 + g * 16 + cc];
                ffma2(acc[0][g], w, h0);
                ffma2(acc[1][g], w, h1);
            }
        }
    }
#pragma unroll
    for (int bb = 0; bb < 2; bb++) {
        int m = m0 + bi0 + bb;
#pragma unroll
        for (int g = 0; g < 4; g++) {
            float lo, hi;
            unpack2(acc[bb][g], lo, hi);
            if (do_relu) { lo = fmaxf(lo, 0.0f); hi = fmaxf(hi, 0.0f); }
            *(float2*)(C + (size_t)m * N + n0 + g * 32 + 2 * cc) = make_float2(lo, hi);
        }
    }
}

// ============================================================================
extern "C" void kernel_launch(void* const* d_in, const int* in_sizes, int n_in,
                              void* d_out, int out_size) {
    const int*   trg   = (const int*)  d_in[2];
    const float* w_ih  = (const float*)d_in[3];
    const float* w_hh  = (const float*)d_in[4];
    const float* b_ih  = (const float*)d_in[5];
    const float* b_hh  = (const float*)d_in[6];
    const float* fc1_w = (const float*)d_in[7];
    const float* fc1_b = (const float*)d_in[8];
    const float* fc2_w = (const float*)d_in[9];
    const float* fc2_b = (const float*)d_in[10];
    float* out = (float*)d_out;

    cudaFuncSetAttribute(lstm_persist,
                         cudaFuncAttributeMaxDynamicSharedMemorySize, SMEMB);

    prep_w<<<2048, 256>>>(w_hh);
    prep_misc<<<256, 256>>>(b_ih, b_hh, w_ih);

    lstm_persist<<<128, 256, SMEMB>>>(trg);

    void* zsym = nullptr;
    cudaGetSymbolAddress(&zsym, g_z);
    float* zptr = (float*)zsym;
    fc_gemm<<<dim3(FC1_N / 128, BATCH / 32), 256>>>(0, fc1_w, fc1_b, zptr, HDIM, FC1_N, 1);
    fc_gemm<<<dim3(FC2_N / 128, BATCH / 32), 256>>>(1, fc2_w, fc2_b, out, FC1_N, FC2_N, 0);
}